// round 9
// baseline (speedup 1.0000x reference)
#include <cuda_runtime.h>

// Problem constants
#define B_  8192
#define T_  336
#define F_  8
#define H_  20
#define G_  80
#define EPB 4            // elements per block (4 elems = 2 packed pairs)

typedef unsigned long long u64;

// Inter-layer hidden sequences, plain element-major float: g_buf[elem][t][unit]
__device__ float g_buf0[(size_t)B_ * T_ * H_];
__device__ float g_buf1[(size_t)B_ * T_ * H_];

// ---- packed f32x2 helpers (sm_103a) ----
__device__ __forceinline__ u64 pk(float lo, float hi) {
    u64 r; asm("mov.b64 %0, {%1, %2};" : "=l"(r) : "f"(lo), "f"(hi)); return r;
}
__device__ __forceinline__ float2 upk(u64 v) {
    float2 f; asm("mov.b64 {%0, %1}, %2;" : "=f"(f.x), "=f"(f.y) : "l"(v)); return f;
}
__device__ __forceinline__ u64 ffma2(u64 a, u64 b, u64 c) {
    u64 d; asm("fma.rn.f32x2 %0, %1, %2, %3;" : "=l"(d) : "l"(a), "l"(b), "l"(c)); return d;
}
__device__ __forceinline__ u64 fmul2(u64 a, u64 b) {
    u64 d; asm("mul.rn.f32x2 %0, %1, %2;" : "=l"(d) : "l"(a), "l"(b)); return d;
}
__device__ __forceinline__ u64 fadd2(u64 a, u64 b) {
    u64 d; asm("add.rn.f32x2 %0, %1, %2;" : "=l"(d) : "l"(a), "l"(b)); return d;
}
__device__ __forceinline__ float sig1(float x) {
    return __fdividef(1.f, 1.f + __expf(-x));
}
__device__ __forceinline__ float hadd2(u64 a, u64 b) {
    float2 f = upk(fadd2(a, b));
    return f.x + f.y;
}

// ============================================================================
// Layer 0: IN=8 float input. 80 threads, 4 elements/block, k-packed weights.
// Critical path per step: 20-slot W_hh·h dot only (x-part pipelined).
// ============================================================================
__global__ __launch_bounds__(80, 12)
void lstm_l0(
    const float* __restrict__ in_seq,
    const float* __restrict__ W_ih,   // [80, 8]
    const float* __restrict__ W_hh,   // [80, 20]
    const float* __restrict__ b_ih,
    const float* __restrict__ b_hh)
{
    constexpr int IN = F_;

    __shared__ __align__(16) float s_h[2][EPB][H_];
    __shared__ __align__(16) float s_x[2][EPB][IN];
    __shared__ u64 s_gt[2][G_];     // gates packed per pair: [pair][gate]

    const int g    = threadIdx.x;   // 0..79
    const int unit = g % H_;
    const int type = g / H_;        // 0..3
    const size_t e0 = (size_t)blockIdx.x * EPB;

    // k-packed weights: whh2[q] = {W_hh[g][2q], W_hh[g][2q+1]}
    u64 whh2[H_ / 2], wih2[IN / 2];
    #pragma unroll
    for (int q = 0; q < H_ / 2; ++q)
        whh2[q] = pk(__ldg(&W_hh[g * H_ + 2 * q]), __ldg(&W_hh[g * H_ + 2 * q + 1]));
    #pragma unroll
    for (int q = 0; q < IN / 2; ++q)
        wih2[q] = pk(__ldg(&W_ih[g * IN + 2 * q]), __ldg(&W_ih[g * IN + 2 * q + 1]));
    const float bias = __ldg(&b_ih[g]) + __ldg(&b_hh[g]);
    const float sc = (type == 2) ? -2.f : -1.f;
    const float am = (type == 2) ?  2.f :  1.f;
    const float bm = (type == 2) ? -1.f :  0.f;

    // staging role: threads 0..31 -> (elem = g/8, feat = g%8)
    const int selem = (g >> 3) & 3, feat = g & 7;
    const float* __restrict__ sp = in_seq + (e0 + selem) * T_ * IN;

    // owner role: type0 -> elems {0,1}, type1 -> elems {2,3}; op in-bounds always
    const int op = type & 1;
    float* __restrict__ dst0 = g_buf0 + (e0 + 2 * op) * T_ * H_;
    float* __restrict__ dst1 = dst0 + (size_t)T_ * H_;

    // prologue
    float xr = 0.f;
    if (g < 32) {
        s_x[0][selem][feat] = sp[feat];
        xr = sp[IN + feat];
    }
    s_h[0][type][unit] = 0.f;
    __syncthreads();

    // xp[E] = bias + W_ih·x[0]
    float xp[EPB];
    #pragma unroll
    for (int E = 0; E < EPB; ++E) {
        const ulonglong2* xv = (const ulonglong2*)s_x[0][E];
        u64 a0 = 0ULL, a1 = 0ULL;
        #pragma unroll
        for (int q = 0; q < IN / 4; ++q) {
            ulonglong2 v = xv[q];
            a0 = ffma2(v.x, wih2[2 * q],     a0);
            a1 = ffma2(v.y, wih2[2 * q + 1], a1);
        }
        xp[E] = bias + hadd2(a0, a1);
    }

    u64 c2 = 0ULL;
    int cur = 0;

    for (int t = 0; t < T_; ++t) {
        // stage x[t+1]; prefetch next
        if (g < 32) {
            s_x[cur ^ 1][selem][feat] = xr;
            const int tn = (t + 2 < T_) ? t + 2 : T_ - 1;
            xr = sp[(size_t)tn * IN + feat];
        }

        // critical: W_hh · h[t-1] per element (k-packed chains)
        float pre[EPB];
        #pragma unroll
        for (int E = 0; E < EPB; ++E) {
            const ulonglong2* hv = (const ulonglong2*)s_h[cur][E];
            u64 a0 = 0ULL, a1 = 0ULL;
            #pragma unroll
            for (int q = 0; q < H_ / 4; ++q) {
                ulonglong2 v = hv[q];
                a0 = ffma2(v.x, whh2[2 * q],     a0);
                a1 = ffma2(v.y, whh2[2 * q + 1], a1);
            }
            pre[E] = xp[E] + hadd2(a0, a1);
        }

        float y[EPB];
        #pragma unroll
        for (int E = 0; E < EPB; ++E) {
            float s = __fdividef(1.f, 1.f + __expf(sc * pre[E]));
            y[E] = fmaf(am, s, bm);
        }
        s_gt[0][g] = pk(y[0], y[1]);
        s_gt[1][g] = pk(y[2], y[3]);

        __syncthreads();

        // owner bubble: cell update for pair `op` (elems 2op, 2op+1)
        if (type < 2) {
            u64 ig = s_gt[op][unit];
            u64 fg = s_gt[op][unit + 20];
            u64 gg = s_gt[op][unit + 40];
            u64 og = s_gt[op][unit + 60];
            c2 = ffma2(fg, c2, fmul2(ig, gg));
            float2 cf = upk(c2);
            float t0 = fmaf(2.f, sig1(2.f * cf.x), -1.f);
            float t1 = fmaf(2.f, sig1(2.f * cf.y), -1.f);
            float2 hf = upk(fmul2(og, pk(t0, t1)));
            s_h[cur ^ 1][2 * op][unit]     = hf.x;
            s_h[cur ^ 1][2 * op + 1][unit] = hf.y;
            dst0[(size_t)t * H_ + unit] = hf.x;
            dst1[(size_t)t * H_ + unit] = hf.y;
        }

        // bubble fill: xp for t+1
        #pragma unroll
        for (int E = 0; E < EPB; ++E) {
            const ulonglong2* xv = (const ulonglong2*)s_x[cur ^ 1][E];
            u64 a0 = 0ULL, a1 = 0ULL;
            #pragma unroll
            for (int q = 0; q < IN / 4; ++q) {
                ulonglong2 v = xv[q];
                a0 = ffma2(v.x, wih2[2 * q],     a0);
                a1 = ffma2(v.y, wih2[2 * q + 1], a1);
            }
            xp[E] = bias + hadd2(a0, a1);
        }

        __syncthreads();
        cur ^= 1;
    }
}

// ============================================================================
// Layers 1/2: IN=20 float input from g_buf. Same structure, all 80 threads
// stage (elem = type, unit). DST: 1 = buf0->buf1 ; 2 = buf1 -> FC -> out
// ============================================================================
template <int DST>
__global__ __launch_bounds__(80, 10)
void lstm_l12(
    const float* __restrict__ W_ih,   // [80, 20]
    const float* __restrict__ W_hh,   // [80, 20]
    const float* __restrict__ b_ih,
    const float* __restrict__ b_hh,
    const float* __restrict__ fc1_w,
    const float* __restrict__ fc1_b,
    const float* __restrict__ fc2_w,
    const float* __restrict__ fc2_b,
    float* __restrict__ out_final)
{
    constexpr bool FINAL = (DST == 2);

    __shared__ __align__(16) float s_h[2][EPB][H_];
    __shared__ __align__(16) float s_x[2][EPB][H_];
    __shared__ u64 s_gt[2][G_];

    const int g    = threadIdx.x;
    const int unit = g % H_;
    const int type = g / H_;
    const size_t e0 = (size_t)blockIdx.x * EPB;

    u64 whh2[H_ / 2], wih2[H_ / 2];
    #pragma unroll
    for (int q = 0; q < H_ / 2; ++q)
        whh2[q] = pk(__ldg(&W_hh[g * H_ + 2 * q]), __ldg(&W_hh[g * H_ + 2 * q + 1]));
    #pragma unroll
    for (int q = 0; q < H_ / 2; ++q)
        wih2[q] = pk(__ldg(&W_ih[g * H_ + 2 * q]), __ldg(&W_ih[g * H_ + 2 * q + 1]));
    const float bias = __ldg(&b_ih[g]) + __ldg(&b_hh[g]);
    const float sc = (type == 2) ? -2.f : -1.f;
    const float am = (type == 2) ?  2.f :  1.f;
    const float bm = (type == 2) ? -1.f :  0.f;

    // staging: every thread stages (elem = type, unit)
    const float* __restrict__ srcBase = (DST == 1) ? g_buf0 : g_buf1;
    const float* __restrict__ sp = srcBase + (e0 + type) * T_ * H_;

    const int op = type & 1;
    float* __restrict__ dst0 = g_buf1 + (e0 + 2 * op) * T_ * H_;
    float* __restrict__ dst1 = dst0 + (size_t)T_ * H_;

    // prologue
    float xr;
    s_x[0][type][unit] = sp[unit];
    xr = sp[H_ + unit];
    s_h[0][type][unit] = 0.f;
    __syncthreads();

    float xp[EPB];
    #pragma unroll
    for (int E = 0; E < EPB; ++E) {
        const ulonglong2* xv = (const ulonglong2*)s_x[0][E];
        u64 a0 = 0ULL, a1 = 0ULL;
        #pragma unroll
        for (int q = 0; q < H_ / 4; ++q) {
            ulonglong2 v = xv[q];
            a0 = ffma2(v.x, wih2[2 * q],     a0);
            a1 = ffma2(v.y, wih2[2 * q + 1], a1);
        }
        xp[E] = bias + hadd2(a0, a1);
    }

    u64 c2 = 0ULL;
    int cur = 0;

    for (int t = 0; t < T_; ++t) {
        s_x[cur ^ 1][type][unit] = xr;
        {
            const int tn = (t + 2 < T_) ? t + 2 : T_ - 1;
            xr = sp[(size_t)tn * H_ + unit];
        }

        float pre[EPB];
        #pragma unroll
        for (int E = 0; E < EPB; ++E) {
            const ulonglong2* hv = (const ulonglong2*)s_h[cur][E];
            u64 a0 = 0ULL, a1 = 0ULL;
            #pragma unroll
            for (int q = 0; q < H_ / 4; ++q) {
                ulonglong2 v = hv[q];
                a0 = ffma2(v.x, whh2[2 * q],     a0);
                a1 = ffma2(v.y, whh2[2 * q + 1], a1);
            }
            pre[E] = xp[E] + hadd2(a0, a1);
        }

        float y[EPB];
        #pragma unroll
        for (int E = 0; E < EPB; ++E) {
            float s = __fdividef(1.f, 1.f + __expf(sc * pre[E]));
            y[E] = fmaf(am, s, bm);
        }
        s_gt[0][g] = pk(y[0], y[1]);
        s_gt[1][g] = pk(y[2], y[3]);

        __syncthreads();

        if (type < 2) {
            u64 ig = s_gt[op][unit];
            u64 fg = s_gt[op][unit + 20];
            u64 gg = s_gt[op][unit + 40];
            u64 og = s_gt[op][unit + 60];
            c2 = ffma2(fg, c2, fmul2(ig, gg));
            float2 cf = upk(c2);
            float t0 = fmaf(2.f, sig1(2.f * cf.x), -1.f);
            float t1 = fmaf(2.f, sig1(2.f * cf.y), -1.f);
            float2 hf = upk(fmul2(og, pk(t0, t1)));
            s_h[cur ^ 1][2 * op][unit]     = hf.x;
            s_h[cur ^ 1][2 * op + 1][unit] = hf.y;
            if (!FINAL) {
                dst0[(size_t)t * H_ + unit] = hf.x;
                dst1[(size_t)t * H_ + unit] = hf.y;
            }
        }

        #pragma unroll
        for (int E = 0; E < EPB; ++E) {
            const ulonglong2* xv = (const ulonglong2*)s_x[cur ^ 1][E];
            u64 a0 = 0ULL, a1 = 0ULL;
            #pragma unroll
            for (int q = 0; q < H_ / 4; ++q) {
                ulonglong2 v = xv[q];
                a0 = ffma2(v.x, wih2[2 * q],     a0);
                a1 = ffma2(v.y, wih2[2 * q + 1], a1);
            }
            xp[E] = bias + hadd2(a0, a1);
        }

        __syncthreads();
        cur ^= 1;
    }

    if (FINAL) {
        // FC head: thread (type, unit) computes dense unit `unit` for elem `type`
        float d = __ldg(&fc1_b[unit]);
        #pragma unroll
        for (int k = 0; k < H_; ++k)
            d = fmaf(s_h[cur][type][k], __ldg(&fc1_w[unit * H_ + k]), d);
        d = fmaxf(d, 0.f);
        ((float*)s_gt)[type * H_ + unit] = d * __ldg(&fc2_w[unit]);
        __syncthreads();
        if (g < EPB) {
            float p = __ldg(&fc2_b[0]);
            #pragma unroll
            for (int k = 0; k < H_; ++k)
                p += ((float*)s_gt)[g * H_ + k];
            out_final[e0 + g] = p;
        }
    }
}

extern "C" void kernel_launch(void* const* d_in, const int* in_sizes, int n_in,
                              void* d_out, int out_size) {
    const float* x     = (const float*)d_in[0];
    const float* Wih0  = (const float*)d_in[1];
    const float* Whh0  = (const float*)d_in[2];
    const float* bih0  = (const float*)d_in[3];
    const float* bhh0  = (const float*)d_in[4];
    const float* Wih1  = (const float*)d_in[5];
    const float* Whh1  = (const float*)d_in[6];
    const float* bih1  = (const float*)d_in[7];
    const float* bhh1  = (const float*)d_in[8];
    const float* Wih2  = (const float*)d_in[9];
    const float* Whh2  = (const float*)d_in[10];
    const float* bih2  = (const float*)d_in[11];
    const float* bhh2  = (const float*)d_in[12];
    const float* fc1w  = (const float*)d_in[13];
    const float* fc1b  = (const float*)d_in[14];
    const float* fc2w  = (const float*)d_in[15];
    const float* fc2b  = (const float*)d_in[16];
    float* out = (float*)d_out;

    const int grid = B_ / EPB;   // 2048

    lstm_l0<<<grid, 80>>>(x, Wih0, Whh0, bih0, bhh0);
    lstm_l12<1><<<grid, 80>>>(
        Wih1, Whh1, bih1, bhh1, nullptr, nullptr, nullptr, nullptr, nullptr);
    lstm_l12<2><<<grid, 80>>>(
        Wih2, Whh2, bih2, bhh2, fc1w, fc1b, fc2w, fc2b, out);
}

// round 10
// speedup vs baseline: 1.0564x; 1.0564x over previous
#include <cuda_runtime.h>

// Problem constants
#define B_  8192
#define T_  336
#define F_  8
#define H_  20
#define G_  80
#define NPAIR (B_ / 2)       // 4096
#define L_  3
#define ITER (T_ + 2 * (L_ - 1))   // 340

typedef unsigned long long u64;

// ---- packed f32x2 helpers (sm_103a) ----
__device__ __forceinline__ u64 pk(float lo, float hi) {
    u64 r; asm("mov.b64 %0, {%1, %2};" : "=l"(r) : "f"(lo), "f"(hi)); return r;
}
__device__ __forceinline__ float2 upk(u64 v) {
    float2 f; asm("mov.b64 {%0, %1}, %2;" : "=f"(f.x), "=f"(f.y) : "l"(v)); return f;
}
__device__ __forceinline__ u64 ffma2(u64 a, u64 b, u64 c) {
    u64 d; asm("fma.rn.f32x2 %0, %1, %2, %3;" : "=l"(d) : "l"(a), "l"(b), "l"(c)); return d;
}
__device__ __forceinline__ u64 fmul2(u64 a, u64 b) {
    u64 d; asm("mul.rn.f32x2 %0, %1, %2;" : "=l"(d) : "l"(a), "l"(b)); return d;
}
__device__ __forceinline__ u64 fadd2(u64 a, u64 b) {
    u64 d; asm("add.rn.f32x2 %0, %1, %2;" : "=l"(d) : "l"(a), "l"(b)); return d;
}
__device__ __forceinline__ float sig1(float x) {
    return __fdividef(1.f, 1.f + __expf(-x));
}

// ============================================================================
// Fully fused 3-layer LSTM + FC head. One block = one element pair.
// 240 threads: thread (l, g) owns gate row g of layer l.
// Wavefront skew 2: layer l at iteration j computes timestep t_l = j - 2l.
// h ring s_h[l][j&3] carries both own-recurrence (read at j+1) and the
// next layer's input (read at j+2), so no intermediate gmem traffic.
// ============================================================================
__global__ __launch_bounds__(240, 2)
void lstm_fused3(
    const float* __restrict__ x,
    const float* __restrict__ W_ih0, const float* __restrict__ W_hh0,
    const float* __restrict__ b_ih0, const float* __restrict__ b_hh0,
    const float* __restrict__ W_ih1, const float* __restrict__ W_hh1,
    const float* __restrict__ b_ih1, const float* __restrict__ b_hh1,
    const float* __restrict__ W_ih2, const float* __restrict__ W_hh2,
    const float* __restrict__ b_ih2, const float* __restrict__ b_hh2,
    const float* __restrict__ fc1_w, const float* __restrict__ fc1_b,
    const float* __restrict__ fc2_w, const float* __restrict__ fc2_b,
    float* __restrict__ out_final)
{
    __shared__ __align__(16) u64 s_h[L_][4][H_];   // hidden ring, element-packed
    __shared__ __align__(16) u64 s_x0[2][H_];      // L0 input (slots 8..19 stay 0)
    __shared__ u64 s_gt[L_][G_];                   // activated gates

    const int tid  = threadIdx.x;
    const int l    = tid / G_;          // layer 0..2
    const int g    = tid % G_;          // gate row 0..79
    const int unit = g % H_;
    const int type = g / H_;
    const size_t pair = blockIdx.x;

    // ---- per-layer weights (dup-packed) ----
    const float* __restrict__ Wih = (l == 0) ? W_ih0 : (l == 1) ? W_ih1 : W_ih2;
    const float* __restrict__ Whh = (l == 0) ? W_hh0 : (l == 1) ? W_hh1 : W_hh2;
    const float* __restrict__ bih = (l == 0) ? b_ih0 : (l == 1) ? b_ih1 : b_ih2;
    const float* __restrict__ bhh = (l == 0) ? b_hh0 : (l == 1) ? b_hh1 : b_hh2;
    const int INl = (l == 0) ? F_ : H_;

    u64 wih2[H_], whh2[H_];
    #pragma unroll
    for (int k = 0; k < H_; ++k) {
        float wi = (k < INl) ? __ldg(&Wih[g * INl + k]) : 0.f;
        wih2[k] = pk(wi, wi);
        float wh = __ldg(&Whh[g * H_ + k]);
        whh2[k] = pk(wh, wh);
    }
    const float bb = __ldg(&bih[g]) + __ldg(&bhh[g]);
    const u64 bias2 = pk(bb, bb);
    const float sc = (type == 2) ? -2.f : -1.f;
    const float am = (type == 2) ?  2.f :  1.f;
    const float bm = (type == 2) ? -1.f :  0.f;

    // L0 gmem staging mapping (threads l==0, g<16): elem = g&1, feat = g>>1
    const int elx = g & 1, feat = g >> 1;
    const float* __restrict__ myin =
        x + (size_t)(2 * pair + elx) * T_ * F_;

    // ---- prologue: zero rings, stage x[0], prefetch x[1] ----
    ((u64*)s_h)[tid] = 0ULL;                 // 3*4*20 = 240 slots, 1/thread
    if (tid < 40) ((u64*)s_x0)[tid] = 0ULL;
    __syncthreads();

    float xr = 0.f;
    if (l == 0 && g < 16) {
        ((float*)&s_x0[0][feat])[elx] = myin[feat];
        xr = myin[F_ + feat];
    }
    __syncthreads();

    // prologue xpart (only L0 needs it at j=0)
    u64 xpA = bias2, xpB = 0ULL;
    if (l == 0) {
        const ulonglong2* xv = (const ulonglong2*)s_x0[0];
        #pragma unroll
        for (int q = 0; q < H_ / 2; ++q) {
            ulonglong2 v = xv[q];
            xpA = ffma2(v.x, wih2[2 * q],     xpA);
            xpB = ffma2(v.y, wih2[2 * q + 1], xpB);
        }
    }

    u64 c2 = 0ULL;

    for (int j = 0; j < ITER; ++j) {
        const int tl = j - 2 * l;
        const bool active = (tl >= 0) && (tl < T_);

        // stage L0 x[j+1]; prefetch x[j+2]
        if (l == 0 && g < 16 && (j + 1) < T_) {
            ((float*)&s_x0[(j + 1) & 1][feat])[elx] = xr;
            const int tn = (j + 2 < T_) ? j + 2 : T_ - 1;
            xr = myin[(size_t)tn * F_ + feat];
        }

        // critical: W_hh · h[t-1]  (xpart carried from previous bubble)
        if (active) {
            const ulonglong2* hv = (const ulonglong2*)s_h[l][(j + 3) & 3];
            u64 a0 = xpA, a1 = xpB;
            #pragma unroll
            for (int q = 0; q < H_ / 2; ++q) {
                ulonglong2 v = hv[q];
                a0 = ffma2(v.x, whh2[2 * q],     a0);
                a1 = ffma2(v.y, whh2[2 * q + 1], a1);
            }
            float2 a = upk(fadd2(a0, a1));
            float y0 = __fdividef(1.f, 1.f + __expf(sc * a.x));
            float y1 = __fdividef(1.f, 1.f + __expf(sc * a.y));
            s_gt[l][g] = pk(fmaf(am, y0, bm), fmaf(am, y1, bm));
        }

        __syncthreads();

        // owner bubble: cell update (20 threads per layer)
        if (active && type == 0) {
            u64 ig = s_gt[l][unit];
            u64 fg = s_gt[l][unit + 20];
            u64 gg = s_gt[l][unit + 40];
            u64 og = s_gt[l][unit + 60];
            c2 = ffma2(fg, c2, fmul2(ig, gg));
            float2 cf = upk(c2);
            float t0 = fmaf(2.f, sig1(2.f * cf.x), -1.f);
            float t1 = fmaf(2.f, sig1(2.f * cf.y), -1.f);
            s_h[l][j & 3][unit] = fmul2(og, pk(t0, t1));
        }

        // bubble fill: xpart for iteration j+1
        const int tln = j + 1 - 2 * l;
        if (tln >= 0 && tln < T_) {
            const ulonglong2* xv = (l == 0)
                ? (const ulonglong2*)s_x0[(j + 1) & 1]
                : (const ulonglong2*)s_h[l - 1][(j + 3) & 3];
            u64 a0 = bias2, a1 = 0ULL;
            #pragma unroll
            for (int q = 0; q < H_ / 2; ++q) {
                ulonglong2 v = xv[q];
                a0 = ffma2(v.x, wih2[2 * q],     a0);
                a1 = ffma2(v.y, wih2[2 * q + 1], a1);
            }
            xpA = a0; xpB = a1;
        }

        __syncthreads();
    }

    // ---- FC head on final h2 (ring slot (ITER-1)&3) ----
    if (l == 2 && type == 0) {
        const u64* hfin = s_h[2][(ITER - 1) & 3];
        float b1 = __ldg(&fc1_b[unit]);
        u64 d2 = pk(b1, b1);
        #pragma unroll
        for (int k = 0; k < H_; ++k) {
            float w = __ldg(&fc1_w[unit * H_ + k]);
            d2 = ffma2(hfin[k], pk(w, w), d2);
        }
        float2 df = upk(d2);
        float wo = __ldg(&fc2_w[unit]);
        s_gt[2][unit] = pk(fmaxf(df.x, 0.f) * wo, fmaxf(df.y, 0.f) * wo);
    }
    __syncthreads();
    if (tid == 2 * G_) {   // l==2, g==0
        float p0 = __ldg(&fc2_b[0]), p1 = p0;
        #pragma unroll
        for (int k = 0; k < H_; ++k) {
            float2 v = upk(s_gt[2][k]);
            p0 += v.x; p1 += v.y;
        }
        out_final[2 * pair]     = p0;
        out_final[2 * pair + 1] = p1;
    }
}

extern "C" void kernel_launch(void* const* d_in, const int* in_sizes, int n_in,
                              void* d_out, int out_size) {
    const float* x     = (const float*)d_in[0];
    const float* Wih0  = (const float*)d_in[1];
    const float* Whh0  = (const float*)d_in[2];
    const float* bih0  = (const float*)d_in[3];
    const float* bhh0  = (const float*)d_in[4];
    const float* Wih1  = (const float*)d_in[5];
    const float* Whh1  = (const float*)d_in[6];
    const float* bih1  = (const float*)d_in[7];
    const float* bhh1  = (const float*)d_in[8];
    const float* Wih2  = (const float*)d_in[9];
    const float* Whh2  = (const float*)d_in[10];
    const float* bih2  = (const float*)d_in[11];
    const float* bhh2  = (const float*)d_in[12];
    const float* fc1w  = (const float*)d_in[13];
    const float* fc1b  = (const float*)d_in[14];
    const float* fc2w  = (const float*)d_in[15];
    const float* fc2b  = (const float*)d_in[16];
    float* out = (float*)d_out;

    lstm_fused3<<<NPAIR, 240>>>(
        x,
        Wih0, Whh0, bih0, bhh0,
        Wih1, Whh1, bih1, bhh1,
        Wih2, Whh2, bih2, bhh2,
        fc1w, fc1b, fc2w, fc2b,
        out);
}

// round 11
// speedup vs baseline: 1.5679x; 1.4841x over previous
#include <cuda_runtime.h>

// Problem constants
#define B_  8192
#define T_  336
#define F_  8
#define H_  20
#define NPAIR (B_ / 2)           // 4096
#define L_  3
#define ITER (T_ + 2 * (L_ - 1)) // 340

typedef unsigned long long u64;

// ---- packed f32x2 helpers (sm_103a) ----
__device__ __forceinline__ u64 pk(float lo, float hi) {
    u64 r; asm("mov.b64 %0, {%1, %2};" : "=l"(r) : "f"(lo), "f"(hi)); return r;
}
__device__ __forceinline__ float2 upk(u64 v) {
    float2 f; asm("mov.b64 {%0, %1}, %2;" : "=f"(f.x), "=f"(f.y) : "l"(v)); return f;
}
__device__ __forceinline__ u64 ffma2(u64 a, u64 b, u64 c) {
    u64 d; asm("fma.rn.f32x2 %0, %1, %2, %3;" : "=l"(d) : "l"(a), "l"(b), "l"(c)); return d;
}
__device__ __forceinline__ u64 fmul2(u64 a, u64 b) {
    u64 d; asm("mul.rn.f32x2 %0, %1, %2;" : "=l"(d) : "l"(a), "l"(b)); return d;
}
__device__ __forceinline__ float sig1(float x) {
    return __fdividef(1.f, 1.f + __expf(-x));
}

// ============================================================================
// Fused 3-layer LSTM + FC head, single barrier per wavefront iteration.
// Block = 1 element pair, 128 threads (120 work + 8 redundant mirrors).
// Work thread (l, r): r = u*2 + half. half0 owns gate rows {u, u+40} (i, g);
// half1 owns {u+20, u+60} (f, o). Gate product i*g crosses to half1 via one
// 64-bit shfl_xor(1); half1 updates the cell and writes h. K-packed weights,
// per-element float h/x vectors ([2][20] floats per ring slot).
// Wavefront skew 2: layer l at iter j computes t = j - 2l.
// ============================================================================
__global__ __launch_bounds__(128, 4)
void lstm_fused3(
    const float* __restrict__ x,
    const float* __restrict__ W_ih0, const float* __restrict__ W_hh0,
    const float* __restrict__ b_ih0, const float* __restrict__ b_hh0,
    const float* __restrict__ W_ih1, const float* __restrict__ W_hh1,
    const float* __restrict__ b_ih1, const float* __restrict__ b_hh1,
    const float* __restrict__ W_ih2, const float* __restrict__ W_hh2,
    const float* __restrict__ b_ih2, const float* __restrict__ b_hh2,
    const float* __restrict__ fc1_w, const float* __restrict__ fc1_b,
    const float* __restrict__ fc2_w, const float* __restrict__ fc2_b,
    float* __restrict__ out_final)
{
    // h ring: [layer][slot][elem][unit]  (written at iter j into slot j&3)
    __shared__ __align__(16) float s_h[L_][4][2][H_];
    // L0 input ring, padded to 20 feats (8..19 stay zero)
    __shared__ __align__(16) float s_x0[4][2][H_];
    __shared__ float s_fc[2][H_];

    const int tid  = threadIdx.x;
    int l = tid / 40; if (l > 2) l = 2;          // tids 120..127 mirror layer 2
    const int r    = (tid - l * 40) % 40;        // 0..39
    const int u    = r >> 1;
    const int half = r & 1;
    const size_t pair = blockIdx.x;

    const int row0 = u + 20 * half;              // i or f
    const int row1 = u + 40 + 20 * half;         // g or o

    const float* __restrict__ Wih = (l == 0) ? W_ih0 : (l == 1) ? W_ih1 : W_ih2;
    const float* __restrict__ Whh = (l == 0) ? W_hh0 : (l == 1) ? W_hh1 : W_hh2;
    const float* __restrict__ bih = (l == 0) ? b_ih0 : (l == 1) ? b_ih1 : b_ih2;
    const float* __restrict__ bhh = (l == 0) ? b_hh0 : (l == 1) ? b_hh1 : b_hh2;
    const int INl = (l == 0) ? F_ : H_;

    // k-packed weights: w[q] = {W[row][2q], W[row][2q+1]}; W_ih zero-padded to 20
    u64 whhA[H_ / 2], whhB[H_ / 2], wihA[H_ / 2], wihB[H_ / 2];
    #pragma unroll
    for (int q = 0; q < H_ / 2; ++q) {
        whhA[q] = pk(__ldg(&Whh[row0 * H_ + 2 * q]), __ldg(&Whh[row0 * H_ + 2 * q + 1]));
        whhB[q] = pk(__ldg(&Whh[row1 * H_ + 2 * q]), __ldg(&Whh[row1 * H_ + 2 * q + 1]));
        float a0 = (2 * q     < INl) ? __ldg(&Wih[row0 * INl + 2 * q])     : 0.f;
        float a1 = (2 * q + 1 < INl) ? __ldg(&Wih[row0 * INl + 2 * q + 1]) : 0.f;
        float b0 = (2 * q     < INl) ? __ldg(&Wih[row1 * INl + 2 * q])     : 0.f;
        float b1 = (2 * q + 1 < INl) ? __ldg(&Wih[row1 * INl + 2 * q + 1]) : 0.f;
        wihA[q] = pk(a0, a1);
        wihB[q] = pk(b0, b1);
    }
    const float bias0 = __ldg(&bih[row0]) + __ldg(&bhh[row0]);
    const float bias1 = __ldg(&bih[row1]) + __ldg(&bhh[row1]);
    // row0 is always sigmoid; row1 is tanh for half0 (g), sigmoid for half1 (o)
    const float sc1 = half ? -1.f : -2.f;
    const float am1 = half ?  1.f :  2.f;
    const float bm1 = half ?  0.f : -1.f;

    // L0 staging role: l==0 && r<16 -> (elx = r&1, feat = r>>1)
    const int elx = r & 1, feat = r >> 1;
    const float* __restrict__ myin = x + (size_t)(2 * pair + elx) * T_ * F_ + feat;

    // ---- zero-init all smem rings ----
    for (int i = tid; i < L_ * 4 * 2 * H_; i += 128) ((float*)s_h)[i] = 0.f;
    for (int i = tid; i < 4 * 2 * H_; i += 128)      ((float*)s_x0)[i] = 0.f;
    __syncthreads();

    // stage x[0], x[1]; prefetch x[2]
    float xr = 0.f;
    if (l == 0 && r < 16) {
        s_x0[0][elx][feat] = myin[0];
        s_x0[1][elx][feat] = myin[(size_t)1 * F_];
        xr = myin[(size_t)2 * F_];
    }
    __syncthreads();

    // K-packed dot over a [2][20]-float vector: 4 independent 10-FFMA2 chains
    #define KDOT(vbase, wA, wB, o00, o01, o10, o11) do {                       \
        const ulonglong2* _v0 = (const ulonglong2*)(vbase);                    \
        const ulonglong2* _v1 = (const ulonglong2*)((vbase) + H_);             \
        u64 _a00 = 0ULL, _a01 = 0ULL, _a10 = 0ULL, _a11 = 0ULL;                \
        _Pragma("unroll")                                                      \
        for (int q = 0; q < 5; ++q) {                                          \
            ulonglong2 _p0 = _v0[q], _p1 = _v1[q];                             \
            _a00 = ffma2(_p0.x, wA[2 * q],     _a00);                          \
            _a00 = ffma2(_p0.y, wA[2 * q + 1], _a00);                          \
            _a01 = ffma2(_p1.x, wA[2 * q],     _a01);                          \
            _a01 = ffma2(_p1.y, wA[2 * q + 1], _a01);                          \
            _a10 = ffma2(_p0.x, wB[2 * q],     _a10);                          \
            _a10 = ffma2(_p0.y, wB[2 * q + 1], _a10);                          \
            _a11 = ffma2(_p1.x, wB[2 * q],     _a11);                          \
            _a11 = ffma2(_p1.y, wB[2 * q + 1], _a11);                          \
        }                                                                      \
        float2 _f;                                                             \
        _f = upk(_a00); o00 = _f.x + _f.y;                                     \
        _f = upk(_a01); o01 = _f.x + _f.y;                                     \
        _f = upk(_a10); o10 = _f.x + _f.y;                                     \
        _f = upk(_a11); o11 = _f.x + _f.y;                                     \
    } while (0)

    // prologue xpart for j=0 (layer0: x slot0; l>0: zeroed h slot 2)
    float xp00, xp01, xp10, xp11;
    {
        const float* vb = (l == 0) ? &s_x0[0][0][0] : &s_h[l - 1][2][0][0];
        KDOT(vb, wihA, wihB, xp00, xp01, xp10, xp11);
        xp00 += bias0; xp01 += bias0; xp10 += bias1; xp11 += bias1;
    }

    u64 c2 = 0ULL;

    for (int j = 0; j < ITER; ++j) {
        const int tl = j - 2 * l;
        const bool active = (tl >= 0) && (tl < T_);

        // stage x[j+2]; prefetch x[j+3]
        if (l == 0 && r < 16) {
            if (j + 2 < T_) s_x0[(j + 2) & 3][elx][feat] = xr;
            const int tn = (j + 3 < T_) ? j + 3 : T_ - 1;
            xr = myin[(size_t)tn * F_];
        }

        // critical: W_hh · h[t-1]  (ring slot (j+3)&3 == (j-1)&3)
        float s00, s01, s10, s11;
        KDOT(&s_h[l][(j + 3) & 3][0][0], whhA, whhB, s00, s01, s10, s11);
        const float p00 = xp00 + s00, p01 = xp01 + s01;
        const float p10 = xp10 + s10, p11 = xp11 + s11;

        // activations (row0 sigmoid; row1 tanh/sigmoid by half)
        const u64 Y0 = pk(sig1(p00), sig1(p01));
        const u64 Y1 = pk(fmaf(am1, __fdividef(1.f, 1.f + __expf(sc1 * p10)), bm1),
                          fmaf(am1, __fdividef(1.f, 1.f + __expf(sc1 * p11)), bm1));

        // half0 ships i*g to half1 (adjacent lane)
        const u64 P = fmul2(Y0, Y1);
        const u64 Precv = __shfl_xor_sync(0xFFFFFFFFu, P, 1);

        if (active && half) {   // half1 holds f (Y0) and o (Y1)
            c2 = ffma2(Y0, c2, Precv);
            float2 cf = upk(c2);
            float t0 = fmaf(2.f, sig1(2.f * cf.x), -1.f);
            float t1 = fmaf(2.f, sig1(2.f * cf.y), -1.f);
            float2 hf = upk(fmul2(Y1, pk(t0, t1)));
            s_h[l][j & 3][0][u] = hf.x;
            s_h[l][j & 3][1][u] = hf.y;
        }

        // bubble: xpart for iter j+1 (inputs synced at previous barrier)
        {
            const float* vb = (l == 0)
                ? &s_x0[(j + 1) & 3][0][0]
                : &s_h[l - 1][(j + 3) & 3][0][0];
            KDOT(vb, wihA, wihB, xp00, xp01, xp10, xp11);
            xp00 += bias0; xp01 += bias0; xp10 += bias1; xp11 += bias1;
        }

        __syncthreads();
    }

    // ---- FC head on layer 2's final h (ring slot (ITER-1)&3 = 3) ----
    if (l == 2) {   // 40 work threads (+8 benign mirrors): elem = half, unit = u
        const float* hfin = &s_h[2][(ITER - 1) & 3][half][0];
        float d = __ldg(&fc1_b[u]);
        #pragma unroll
        for (int k = 0; k < H_; ++k)
            d = fmaf(hfin[k], __ldg(&fc1_w[u * H_ + k]), d);
        d = fmaxf(d, 0.f);
        s_fc[half][u] = d * __ldg(&fc2_w[u]);
    }
    __syncthreads();
    if (tid == 80 || tid == 81) {   // layer-2 r=0 (half0) and r=1 (half1)
        const int po = tid - 80;
        float p = __ldg(&fc2_b[0]);
        #pragma unroll
        for (int k = 0; k < H_; ++k) p += s_fc[po][k];
        out_final[2 * pair + po] = p;
    }
}

extern "C" void kernel_launch(void* const* d_in, const int* in_sizes, int n_in,
                              void* d_out, int out_size) {
    const float* x     = (const float*)d_in[0];
    const float* Wih0  = (const float*)d_in[1];
    const float* Whh0  = (const float*)d_in[2];
    const float* bih0  = (const float*)d_in[3];
    const float* bhh0  = (const float*)d_in[4];
    const float* Wih1  = (const float*)d_in[5];
    const float* Whh1  = (const float*)d_in[6];
    const float* bih1  = (const float*)d_in[7];
    const float* bhh1  = (const float*)d_in[8];
    const float* Wih2  = (const float*)d_in[9];
    const float* Whh2  = (const float*)d_in[10];
    const float* bih2  = (const float*)d_in[11];
    const float* bhh2  = (const float*)d_in[12];
    const float* fc1w  = (const float*)d_in[13];
    const float* fc1b  = (const float*)d_in[14];
    const float* fc2w  = (const float*)d_in[15];
    const float* fc2b  = (const float*)d_in[16];
    float* out = (float*)d_out;

    lstm_fused3<<<NPAIR, 128>>>(
        x,
        Wih0, Whh0, bih0, bhh0,
        Wih1, Whh1, bih1, bhh1,
        Wih2, Whh2, bih2, bhh2,
        fc1w, fc1b, fc2w, fc2b,
        out);
}